// round 12
// baseline (speedup 1.0000x reference)
#include <cuda_runtime.h>
#include <cuda_bf16.h>
#include <cuda_fp16.h>
#include <cstdint>

// x (12,64,256,256) f32, w (64,64,3,3) f32, out (12,64,256,256) f32
// channel-shift (roll 32 over T*C=192) -> sign -> 3x3 same-pad conv, weights sign(w)*mean|w|[o]
// Persistent: 148 CTAs x 512 thr, tile M=256 px (8x32), N=64, K=576.
// fp16 mma.sync m16n8k16 with fp16 accumulation — EXACT: all partial sums are
// integers |v| <= 576 < 2048, exactly representable in fp16.

#define NT      3072           // 12 images * 32 h-tiles * 8 w-tiles (tile = 8x32 px)
#define GRIDN   148
#define THREADS 512

__device__ float g_scale[64];
__device__ uint2 g_Bpack[9 * 4 * 8 * 32];   // [tap][kt4][nt8][lane] -> (b0,b1) fp16 frags, 73728 B

// smem: B 73728 | A0 43520 (340 px * 128B) | A1 43520 | scale 256 = 161024
#define SM_A0    73728
#define SM_A1    117248
#define SM_SC    160768
#define SMEM_DYN 161024

__device__ __forceinline__ uint32_t sign_f16_bits(float x) {
    uint32_t u = __float_as_uint(x);
    uint32_t mag = u & 0x7FFFFFFFu;
    uint32_t s = (u >> 16) & 0x8000u;
    return mag ? (0x3C00u | s) : 0u;     // +-1.0 fp16, 0 if x==0
}

// -------------------- weight prep --------------------

__global__ void prep_scale_kernel(const float* __restrict__ w) {
    int o = blockIdx.x, tid = threadIdx.x;
    float s = 0.f;
    for (int i = tid; i < 576; i += 256) s += fabsf(w[o * 576 + i]);
    #pragma unroll
    for (int off = 16; off; off >>= 1) s += __shfl_down_sync(0xFFFFFFFFu, s, off);
    __shared__ float red[8];
    if ((tid & 31) == 0) red[tid >> 5] = s;
    __syncthreads();
    if (tid < 8) {
        float v = red[tid];
        #pragma unroll
        for (int off = 4; off; off >>= 1) v += __shfl_down_sync(0xFFu, v, off);
        if (tid == 0) g_scale[o] = v * (1.0f / 576.0f);
    }
}

__global__ void prep_weights_kernel(const float* __restrict__ w) {
    int tap = blockIdx.x;         // 0..8
    int kt  = blockIdx.y;         // 0..3
    int tid = threadIdx.x;        // 256
    int nt = tid >> 5, lane = tid & 31;
    int tig = lane & 3, g = lane >> 2;
    int o = nt * 8 + g;
    uint32_t e[4];
    #pragma unroll
    for (int j = 0; j < 4; j++) {
        int k = (j < 2) ? (2 * tig + j) : (2 * tig + 8 + (j - 2));
        int c = kt * 16 + k;
        e[j] = sign_f16_bits(w[(o * 64 + c) * 9 + tap]);
    }
    g_Bpack[((tap * 4 + kt) * 8 + nt) * 32 + lane] = make_uint2(e[0] | (e[1] << 16), e[2] | (e[3] << 16));
}

// -------------------- tile loader (scalar coalesced, half-split; R11-validated) --------------------
// A tile: 10 rows x 34 cols = 340 halo pixels, [pixel][64ch fp16], 128B rows,
// byte(pix, c) = pix*128 + ((2c) ^ ((pix&7)<<4))

__device__ __forceinline__ void load_tile(const float* __restrict__ x, unsigned char* sA,
                                          int tid, int b, int t, int h0, int w0) {
    #pragma unroll
    for (int rep = 0; rep < 2; rep++) {
        int task = tid + rep * 512;
        if (task >= 680) break;
        int half = task & 1;
        int pix = task >> 1;
        int pr = pix / 34, pc = pix - pr * 34;
        int h = h0 - 1 + pr, ww = w0 - 1 + pc;
        bool valid = ((unsigned)h < 256u) && ((unsigned)ww < 256u);
        int fb = t * 64 + half * 32 - 32; if (fb < 0) fb += 192;   // contiguous 32-ch block
        const float* xb = x + (long)(b * 192 + fb) * 65536 + (h * 256 + ww);
        uint32_t wd[16];
        #pragma unroll
        for (int q = 0; q < 16; q++) {
            uint32_t lo = 0, hi = 0;
            if (valid) {
                lo = sign_f16_bits(__ldg(xb + ((long)(2 * q) << 16)));
                hi = sign_f16_bits(__ldg(xb + ((long)(2 * q + 1) << 16)));
            }
            wd[q] = lo | (hi << 16);
        }
        unsigned char* row = sA + pix * 128;
        uint32_t pw7 = (uint32_t)(pix & 7);
        #pragma unroll
        for (int j = 0; j < 4; j++) {
            uint32_t chunk = ((uint32_t)(half * 4 + j)) ^ pw7;
            *reinterpret_cast<uint4*>(row + (chunk << 4)) =
                make_uint4(wd[4 * j], wd[4 * j + 1], wd[4 * j + 2], wd[4 * j + 3]);
        }
    }
}

// -------------------- persistent fused kernel --------------------

__global__ void __launch_bounds__(THREADS, 1)
conv_kernel(const float* __restrict__ x, float* __restrict__ out) {
    extern __shared__ unsigned char smem[];
    uint2* sB = reinterpret_cast<uint2*>(smem);
    float* sScale = reinterpret_cast<float*>(smem + SM_SC);

    const int tid = threadIdx.x;
    const int bid = blockIdx.x;

    // stage B once (4608 uint4 / 512 thr = 9 each) + scales
    {
        const uint4* src = reinterpret_cast<const uint4*>(g_Bpack);
        uint4* dst = reinterpret_cast<uint4*>(smem);
        #pragma unroll
        for (int k = 0; k < 9; k++) dst[tid + k * 512] = src[tid + k * 512];
    }
    if (tid < 64) sScale[tid] = g_scale[tid];

    const int warp = tid >> 5, lane = tid & 31;
    const int ph  = warp >> 1;               // tile row 0..7
    const int pw0 = (warp & 1) * 16;         // tile col base 0/16
    const int tig = lane & 3, g = lane >> 2;
    const int mrow = lane & 15;
    const int khalf = lane >> 4;

    const int n_my = (NT - 1 - bid) / GRIDN + 1;

    // preload tile 0
    {
        int tl = bid;
        int bt = tl >> 8, rem = tl & 255;
        load_tile(x, smem + SM_A0, tid, bt / 3, bt % 3, (rem >> 3) * 8, (rem & 7) * 32);
    }
    __syncthreads();

    for (int it = 0; it < n_my; it++) {
        const int tl = bid + it * GRIDN;
        const int bt = tl >> 8, rem = tl & 255;
        const int h0 = (rem >> 3) * 8, w0 = (rem & 7) * 32;

        // issue next tile's loads into the other buffer (overlaps mainloop below)
        if (it + 1 < n_my) {
            int tl2 = bid + (it + 1) * GRIDN;
            int bt2 = tl2 >> 8, rem2 = tl2 & 255;
            load_tile(x, smem + (((it + 1) & 1) ? SM_A1 : SM_A0), tid,
                      bt2 / 3, bt2 % 3, (rem2 >> 3) * 8, (rem2 & 7) * 32);
        }

        // ---- mainloop on current buffer: fp16-accum HMMA ----
        const unsigned char* sA = smem + ((it & 1) ? SM_A1 : SM_A0);
        const uint32_t sA_base = (uint32_t)__cvta_generic_to_shared(sA);

        uint32_t acc[8][2];
        #pragma unroll
        for (int nt = 0; nt < 8; nt++) { acc[nt][0] = 0u; acc[nt][1] = 0u; }

        #pragma unroll
        for (int tap = 0; tap < 9; tap++) {
            const int kh = tap / 3, kw = tap - kh * 3;
            const int pix = (ph + kh) * 34 + pw0 + kw + mrow;
            const uint32_t pix_sw = ((uint32_t)pix & 7u) << 4;
            #pragma unroll
            for (int kt = 0; kt < 4; kt++) {
                uint32_t a0, a1, a2, a3;
                uint32_t addr = sA_base + (uint32_t)pix * 128u
                              + (((uint32_t)(kt * 32 + khalf * 16)) ^ pix_sw);
                asm volatile("ldmatrix.sync.aligned.x4.m8n8.shared.b16 {%0,%1,%2,%3}, [%4];"
                             : "=r"(a0), "=r"(a1), "=r"(a2), "=r"(a3) : "r"(addr));
                #pragma unroll
                for (int nt = 0; nt < 8; nt++) {
                    uint2 bb = sB[((tap * 4 + kt) * 8 + nt) * 32 + lane];
                    asm volatile(
                        "mma.sync.aligned.m16n8k16.row.col.f16.f16.f16.f16 "
                        "{%0,%1}, {%2,%3,%4,%5}, {%6,%7}, {%0,%1};"
                        : "+r"(acc[nt][0]), "+r"(acc[nt][1])
                        : "r"(a0), "r"(a1), "r"(a2), "r"(a3), "r"(bb.x), "r"(bb.y));
                }
            }
        }

        // ---- epilogue: unpack half2 (exact integers), scale, store ----
        {
            const int hh = h0 + ph;
            const int wb = w0 + pw0 + g;
            #pragma unroll
            for (int nt = 0; nt < 8; nt++) {
                int o0 = nt * 8 + 2 * tig;
                float s0 = sScale[o0], s1 = sScale[o0 + 1];
                long base0 = ((long)(bt * 64 + o0) << 16) + (hh << 8) + wb;
                long base1 = base0 + 65536;
                float2 f0 = __half22float2(*reinterpret_cast<__half2*>(&acc[nt][0]));
                float2 f1 = __half22float2(*reinterpret_cast<__half2*>(&acc[nt][1]));
                out[base0]     = s0 * f0.x;
                out[base1]     = s1 * f0.y;
                out[base0 + 8] = s0 * f1.x;
                out[base1 + 8] = s1 * f1.y;
            }
        }
        __syncthreads();   // next buffer's STS visible; safe to overwrite current next iter
    }
}

// -------------------- launch --------------------

extern "C" void kernel_launch(void* const* d_in, const int* in_sizes, int n_in,
                              void* d_out, int out_size) {
    const float* x = (const float*)d_in[0];
    const float* w = (const float*)d_in[1];
    float* out = (float*)d_out;

    cudaFuncSetAttribute(conv_kernel, cudaFuncAttributeMaxDynamicSharedMemorySize, SMEM_DYN);

    prep_scale_kernel<<<64, 256>>>(w);
    prep_weights_kernel<<<dim3(9, 4, 1), 256>>>(w);
    conv_kernel<<<GRIDN, THREADS, SMEM_DYN>>>(x, out);
}

// round 14
// speedup vs baseline: 1.0722x; 1.0722x over previous
#include <cuda_runtime.h>
#include <cuda_bf16.h>
#include <cuda_fp16.h>
#include <cstdint>

// x (12,64,256,256) f32, w (64,64,3,3) f32, out (12,64,256,256) f32
// channel-shift (roll 32 over T*C=192) -> sign -> 3x3 same-pad conv, weights sign(w)*mean|w|[o]
// Persistent: 148 CTAs x 512 thr, tile M=256 px (8x32), N=64, K=576.
// fp16 mma m16n8k16, fp16 accum (exact: integer partial sums <= 576 < 2048).
// Loader for tile it+1 is software-pipelined through the 9-tap mainloop of tile it.

#define NT      3072           // 12 images * 32 h-tiles * 8 w-tiles (tile = 8x32 px)
#define GRIDN   148
#define THREADS 512

__device__ float g_scale[64];
__device__ uint2 g_Bpack[9 * 4 * 8 * 32];   // [tap][kt4][nt8][lane] -> (b0,b1) fp16 frags, 73728 B

// smem: B 73728 | A0 43520 (340 px * 128B) | A1 43520 | scale 256 = 161024
#define SM_A0    73728
#define SM_A1    117248
#define SM_SC    160768
#define SMEM_DYN 161024

__device__ __forceinline__ uint32_t sign_f16_bits(float x) {
    uint32_t u = __float_as_uint(x);
    uint32_t mag = u & 0x7FFFFFFFu;
    uint32_t s = (u >> 16) & 0x8000u;
    return mag ? (0x3C00u | s) : 0u;     // +-1.0 fp16, 0 if x==0
}

// -------------------- weight prep (validated) --------------------

__global__ void prep_scale_kernel(const float* __restrict__ w) {
    int o = blockIdx.x, tid = threadIdx.x;
    float s = 0.f;
    for (int i = tid; i < 576; i += 256) s += fabsf(w[o * 576 + i]);
    #pragma unroll
    for (int off = 16; off; off >>= 1) s += __shfl_down_sync(0xFFFFFFFFu, s, off);
    __shared__ float red[8];
    if ((tid & 31) == 0) red[tid >> 5] = s;
    __syncthreads();
    if (tid < 8) {
        float v = red[tid];
        #pragma unroll
        for (int off = 4; off; off >>= 1) v += __shfl_down_sync(0xFFu, v, off);
        if (tid == 0) g_scale[o] = v * (1.0f / 576.0f);
    }
}

__global__ void prep_weights_kernel(const float* __restrict__ w) {
    int tap = blockIdx.x;         // 0..8
    int kt  = blockIdx.y;         // 0..3
    int tid = threadIdx.x;        // 256
    int nt = tid >> 5, lane = tid & 31;
    int tig = lane & 3, g = lane >> 2;
    int o = nt * 8 + g;
    uint32_t e[4];
    #pragma unroll
    for (int j = 0; j < 4; j++) {
        int k = (j < 2) ? (2 * tig + j) : (2 * tig + 8 + (j - 2));
        int c = kt * 16 + k;
        e[j] = sign_f16_bits(w[(o * 64 + c) * 9 + tap]);
    }
    g_Bpack[((tap * 4 + kt) * 8 + nt) * 32 + lane] = make_uint2(e[0] | (e[1] << 16), e[2] | (e[3] << 16));
}

// -------------------- monolithic loader (startup only; R11-validated) --------------------
// A tile: 10 rows x 34 cols = 340 halo pixels, [pixel][64ch fp16], 128B rows,
// byte(pix, c) = pix*128 + ((2c) ^ ((pix&7)<<4))

__device__ __forceinline__ void load_tile(const float* __restrict__ x, unsigned char* sA,
                                          int tid, int b, int t, int h0, int w0) {
    #pragma unroll
    for (int rep = 0; rep < 2; rep++) {
        int task = tid + rep * 512;
        if (task >= 680) break;
        int half = task & 1;
        int pix = task >> 1;
        int pr = pix / 34, pc = pix - pr * 34;
        int h = h0 - 1 + pr, ww = w0 - 1 + pc;
        bool valid = ((unsigned)h < 256u) && ((unsigned)ww < 256u);
        int fb = t * 64 + half * 32 - 32; if (fb < 0) fb += 192;
        const float* xb = x + (long)(b * 192 + fb) * 65536 + (h * 256 + ww);
        uint32_t wd[16];
        #pragma unroll
        for (int q = 0; q < 16; q++) {
            uint32_t lo = 0, hi = 0;
            if (valid) {
                lo = sign_f16_bits(__ldg(xb + ((long)(2 * q) << 16)));
                hi = sign_f16_bits(__ldg(xb + ((long)(2 * q + 1) << 16)));
            }
            wd[q] = lo | (hi << 16);
        }
        unsigned char* row = sA + pix * 128;
        uint32_t pw7 = (uint32_t)(pix & 7);
        #pragma unroll
        for (int j = 0; j < 4; j++) {
            uint32_t chunk = ((uint32_t)(half * 4 + j)) ^ pw7;
            *reinterpret_cast<uint4*>(row + (chunk << 4)) =
                make_uint4(wd[4 * j], wd[4 * j + 1], wd[4 * j + 2], wd[4 * j + 3]);
        }
    }
}

// -------------------- persistent fused kernel --------------------

__global__ void __launch_bounds__(THREADS, 1)
conv_kernel(const float* __restrict__ x, float* __restrict__ out) {
    extern __shared__ unsigned char smem[];
    uint2* sB = reinterpret_cast<uint2*>(smem);
    float* sScale = reinterpret_cast<float*>(smem + SM_SC);

    const int tid = threadIdx.x;
    const int bid = blockIdx.x;

    // stage B once (4608 uint4 / 512 thr = 9 each) + scales
    {
        const uint4* src = reinterpret_cast<const uint4*>(g_Bpack);
        uint4* dst = reinterpret_cast<uint4*>(smem);
        #pragma unroll
        for (int k = 0; k < 9; k++) dst[tid + k * 512] = src[tid + k * 512];
    }
    if (tid < 64) sScale[tid] = g_scale[tid];

    const int warp = tid >> 5, lane = tid & 31;
    const int ph  = warp >> 1;               // tile row 0..7
    const int pw0 = (warp & 1) * 16;         // tile col base 0/16
    const int tig = lane & 3, g = lane >> 2;
    const int mrow = lane & 15;
    const int khalf = lane >> 4;

    const int n_my = (NT - 1 - bid) / GRIDN + 1;

    // preload tile 0
    {
        int tl = bid;
        int bt = tl >> 8, rem = tl & 255;
        load_tile(x, smem + SM_A0, tid, bt / 3, bt % 3, (rem >> 3) * 8, (rem & 7) * 32);
    }
    __syncthreads();

    for (int it = 0; it < n_my; it++) {
        const int tl = bid + it * GRIDN;
        const int bt = tl >> 8, rem = tl & 255;
        const int h0 = (rem >> 3) * 8, w0 = (rem & 7) * 32;

        // ---- set up pipelined loader state for tile it+1 ----
        const bool hasnext = (it + 1 < n_my);
        const float* xbp[2];
        unsigned char* rowp[2];
        uint32_t hb4[2], p7[2];
        bool act[2], vld[2];
        {
            int tl2 = hasnext ? (bid + (it + 1) * GRIDN) : 0;
            int bt2 = tl2 >> 8, rem2 = tl2 & 255;
            int b2 = bt2 / 3, t2 = bt2 % 3;
            int h0n = (rem2 >> 3) * 8, w0n = (rem2 & 7) * 32;
            unsigned char* nbuf = smem + (((it + 1) & 1) ? SM_A1 : SM_A0);
            #pragma unroll
            for (int r = 0; r < 2; r++) {
                int task = tid + r * 512;
                act[r] = hasnext && (task < 680);
                int half = task & 1, pix = (task >> 1) % 340;
                int pr = pix / 34, pc = pix - pr * 34;
                int h = h0n - 1 + pr, ww = w0n - 1 + pc;
                vld[r] = act[r] && ((unsigned)h < 256u) && ((unsigned)ww < 256u);
                int fb = t2 * 64 + half * 32 - 32; if (fb < 0) fb += 192;
                xbp[r] = x + (long)(b2 * 192 + fb) * 65536 + (h * 256 + ww);
                rowp[r] = nbuf + pix * 128;
                hb4[r] = (uint32_t)(half * 4);
                p7[r]  = (uint32_t)(pix & 7);
            }
        }
        float fl[8];

        #define LD_ISSUE(R, SUB) do {                                              \
            if (vld[R]) {                                                          \
                _Pragma("unroll")                                                  \
                for (int m = 0; m < 4; m++) {                                      \
                    int q = (SUB) * 4 + m;                                         \
                    fl[2 * m]     = __ldg(xbp[R] + ((long)(2 * q) << 16));          \
                    fl[2 * m + 1] = __ldg(xbp[R] + ((long)(2 * q + 1) << 16));      \
                }                                                                  \
            } else {                                                               \
                _Pragma("unroll")                                                  \
                for (int m = 0; m < 8; m++) fl[m] = 0.f;                           \
            } } while (0)

        #define LD_FLUSH(R, SUB) do {                                              \
            if (act[R]) {                                                          \
                uint32_t w0_ = sign_f16_bits(fl[0]) | (sign_f16_bits(fl[1]) << 16); \
                uint32_t w1_ = sign_f16_bits(fl[2]) | (sign_f16_bits(fl[3]) << 16); \
                uint32_t w2_ = sign_f16_bits(fl[4]) | (sign_f16_bits(fl[5]) << 16); \
                uint32_t w3_ = sign_f16_bits(fl[6]) | (sign_f16_bits(fl[7]) << 16); \
                uint32_t ch = (hb4[R] + (uint32_t)(SUB)) ^ p7[R];                   \
                *reinterpret_cast<uint4*>(rowp[R] + (ch << 4)) =                    \
                    make_uint4(w0_, w1_, w2_, w3_);                                 \
            } } while (0)

        // ---- mainloop on current buffer, loader chunks interleaved per tap ----
        const unsigned char* sA = smem + ((it & 1) ? SM_A1 : SM_A0);
        const uint32_t sA_base = (uint32_t)__cvta_generic_to_shared(sA);

        uint32_t acc[8][2];
        #pragma unroll
        for (int nt = 0; nt < 8; nt++) { acc[nt][0] = 0u; acc[nt][1] = 0u; }

        LD_ISSUE(0, 0);    // chunk 0 in flight before tap 0

        #pragma unroll
        for (int tap = 0; tap < 9; tap++) {
            const int kh = tap / 3, kw = tap - kh * 3;
            const int pix = (ph + kh) * 34 + pw0 + kw + mrow;
            const uint32_t pix_sw = ((uint32_t)pix & 7u) << 4;
            #pragma unroll
            for (int kt = 0; kt < 4; kt++) {
                uint32_t a0, a1, a2, a3;
                uint32_t addr = sA_base + (uint32_t)pix * 128u
                              + (((uint32_t)(kt * 32 + khalf * 16)) ^ pix_sw);
                asm volatile("ldmatrix.sync.aligned.x4.m8n8.shared.b16 {%0,%1,%2,%3}, [%4];"
                             : "=r"(a0), "=r"(a1), "=r"(a2), "=r"(a3) : "r"(addr));
                #pragma unroll
                for (int nt = 0; nt < 8; nt++) {
                    uint2 bb = sB[((tap * 4 + kt) * 8 + nt) * 32 + lane];
                    asm volatile(
                        "mma.sync.aligned.m16n8k16.row.col.f16.f16.f16.f16 "
                        "{%0,%1}, {%2,%3,%4,%5}, {%6,%7}, {%0,%1};"
                        : "+r"(acc[nt][0]), "+r"(acc[nt][1])
                        : "r"(a0), "r"(a1), "r"(a2), "r"(a3), "r"(bb.x), "r"(bb.y));
                }
            }
            // consume chunk `tap` (loads issued one full tap ago), issue chunk tap+1
            if (tap < 8) {
                const int rp = tap >> 2, sb = tap & 3;
                if (rp == 0) { LD_FLUSH(0, sb); } else { LD_FLUSH(1, sb); }
                const int tn = tap + 1;
                if (tn < 8) {
                    const int rp2 = tn >> 2, sb2 = tn & 3;
                    if (rp2 == 0) { LD_ISSUE(0, sb2); } else { LD_ISSUE(1, sb2); }
                }
            }
        }

        #undef LD_ISSUE
        #undef LD_FLUSH

        // ---- epilogue: unpack half2 (exact integers), scale, store ----
        {
            const int hh = h0 + ph;
            const int wb = w0 + pw0 + g;
            #pragma unroll
            for (int nt = 0; nt < 8; nt++) {
                int o0 = nt * 8 + 2 * tig;
                float s0 = sScale[o0], s1 = sScale[o0 + 1];
                long base0 = ((long)(bt * 64 + o0) << 16) + (hh << 8) + wb;
                long base1 = base0 + 65536;
                float2 f0 = __half22float2(*reinterpret_cast<__half2*>(&acc[nt][0]));
                float2 f1 = __half22float2(*reinterpret_cast<__half2*>(&acc[nt][1]));
                out[base0]     = s0 * f0.x;
                out[base1]     = s1 * f0.y;
                out[base0 + 8] = s0 * f1.x;
                out[base1 + 8] = s1 * f1.y;
            }
        }
        __syncthreads();   // next buffer fully written & visible; current safe to overwrite
    }
}

// -------------------- launch --------------------

extern "C" void kernel_launch(void* const* d_in, const int* in_sizes, int n_in,
                              void* d_out, int out_size) {
    const float* x = (const float*)d_in[0];
    const float* w = (const float*)d_in[1];
    float* out = (float*)d_out;

    cudaFuncSetAttribute(conv_kernel, cudaFuncAttributeMaxDynamicSharedMemorySize, SMEM_DYN);

    prep_scale_kernel<<<64, 256>>>(w);
    prep_weights_kernel<<<dim3(9, 4, 1), 256>>>(w);
    conv_kernel<<<GRIDN, THREADS, SMEM_DYN>>>(x, out);
}